// round 1
// baseline (speedup 1.0000x reference)
#include <cuda_runtime.h>

#define NANCH 19200      // 3*80*80 anchors per image
#define NIMG  8
#define MTGT  100
#define NCLS  80
#define THREADS 256
#define NBLK_PER_IMG (NANCH / THREADS)   // 75
#define NBLOCKS (NIMG * NBLK_PER_IMG)    // 600

__device__ float g_part[NBLOCKS * 4];

// Deterministic block reduction (fixed pairing order). Result valid on tid 0.
__device__ __forceinline__ float block_reduce(float v, float* red) {
    int tid = threadIdx.x;
    #pragma unroll
    for (int o = 16; o > 0; o >>= 1) v += __shfl_down_sync(0xFFFFFFFFu, v, o);
    if ((tid & 31) == 0) red[tid >> 5] = v;
    __syncthreads();
    float r = 0.0f;
    if (tid == 0) {
        #pragma unroll
        for (int w = 0; w < THREADS / 32; w++) r += red[w];
    }
    __syncthreads();
    return r;
}

__global__ void __launch_bounds__(THREADS) loss_main(
    const float* __restrict__ obj,    // [8,19200]
    const float* __restrict__ boxes,  // [8,19200,4] (cx,cy,w,h)
    const float* __restrict__ cls,    // [8,19200,80]
    const float* __restrict__ tbox,   // [8,100,4]
    const int*   __restrict__ tlab)   // [8,100]
{
    __shared__ float4 s_lohi[MTGT];       // lox,loy,hix,hiy
    __shared__ float  s_area[MTGT];
    __shared__ int    s_lab[MTGT];
    __shared__ int    s_warp_cnt[THREADS / 32];
    __shared__ int    s_pos_row[THREADS]; // global anchor row of positives
    __shared__ int    s_pos_lab[THREADS];
    __shared__ float  red[THREADS / 32];

    const int tid  = threadIdx.x;
    const int img  = blockIdx.x / NBLK_PER_IMG;
    const int ablk = blockIdx.x % NBLK_PER_IMG;
    const int arow = img * NANCH + ablk * THREADS + tid;

    // Preprocess targets of this image into shared (lo/hi/area)
    if (tid < MTGT) {
        float4 tb = ((const float4*)tbox)[img * MTGT + tid];
        float lox = tb.x - 0.5f * tb.z, loy = tb.y - 0.5f * tb.w;
        float hix = tb.x + 0.5f * tb.z, hiy = tb.y + 0.5f * tb.w;
        s_lohi[tid] = make_float4(lox, loy, hix, hiy);
        s_area[tid] = tb.z * tb.w;
        s_lab[tid]  = tlab[img * MTGT + tid];
    }
    __syncthreads();

    // Anchor box
    float4 bx = ((const float4*)boxes)[arow];
    float lo1x = bx.x - 0.5f * bx.z, lo1y = bx.y - 0.5f * bx.w;
    float hi1x = bx.x + 0.5f * bx.z, hi1y = bx.y + 0.5f * bx.w;
    float a1   = bx.z * bx.w;

    // Division-free argmax of IoU: compare i_c/u_c vs i_b/u_b via cross-mult (u > 0)
    float bi = -1.0f, bu = 1.0f;
    int   bidx = 0;
    #pragma unroll 4
    for (int m = 0; m < MTGT; m++) {
        float4 t = s_lohi[m];
        float wx = fminf(hi1x, t.z) - fmaxf(lo1x, t.x);
        float wy = fminf(hi1y, t.w) - fmaxf(lo1y, t.y);
        wx = fmaxf(wx, 0.0f);
        wy = fmaxf(wy, 0.0f);
        float inter = wx * wy;
        float u = a1 + s_area[m] - inter + 1e-6f;
        if (inter * bu > bi * u) { bi = inter; bu = u; bidx = m; }
    }
    bool pos = (bi >= 0.5f * bu);   // max_iou >= 0.5
    float posf = pos ? 1.0f : 0.0f;

    // Objectness BCE (only the selected term contributes)
    float o = obj[arow];
    float bce = pos ? -fmaxf(logf(o), -100.0f)
                    : -fmaxf(log1pf(-o), -100.0f);

    // GIoU bbox loss — positives only (negatives multiplied by 0 in reference)
    float bbox = 0.0f;
    if (pos) {
        float4 t = s_lohi[bidx];
        float wx = fmaxf(fminf(hi1x, t.z) - fmaxf(lo1x, t.x), 0.0f);
        float wy = fmaxf(fminf(hi1y, t.w) - fmaxf(lo1y, t.y), 0.0f);
        float inter = wx * wy;
        float uni = a1 + s_area[bidx] - inter;
        float iou = __fdividef(inter, uni + 1e-6f);
        float ex = fmaxf(fmaxf(hi1x, t.z) - fminf(lo1x, t.x), 0.0f);
        float ey = fmaxf(fmaxf(hi1y, t.w) - fminf(lo1y, t.y), 0.0f);
        float enc = ex * ey;
        float giou = iou - __fdividef(enc - uni, enc + 1e-6f);
        bbox = 1.0f - giou;
    }

    // Deterministic compaction of positives (ballot scan, fixed thread order)
    unsigned ball = __ballot_sync(0xFFFFFFFFu, pos);
    int wid = tid >> 5, lane = tid & 31;
    if (lane == 0) s_warp_cnt[wid] = __popc(ball);
    __syncthreads();
    int wbase = 0;
    #pragma unroll
    for (int w = 0; w < THREADS / 32; w++) wbase += (w < wid) ? s_warp_cnt[w] : 0;
    int P = 0;
    #pragma unroll
    for (int w = 0; w < THREADS / 32; w++) P += s_warp_cnt[w];
    if (pos) {
        int myofs = wbase + __popc(ball & ((1u << lane) - 1u));
        s_pos_row[myofs] = arow;
        s_pos_lab[myofs] = s_lab[bidx];
    }
    __syncthreads();

    // Focal loss over positives only: items = P * 80, cooperative across block.
    float fl = 0.0f;
    const int items = P * NCLS;
    for (int i = tid; i < items; i += THREADS) {
        int a = i / NCLS;
        int c = i - a * NCLS;
        int row = s_pos_row[a];
        float x = cls[row * NCLS + c];
        bool t = (c == s_pos_lab[a]);
        float e  = __expf(-fabsf(x));
        float sp = __logf(1.0f + e);                // log1p(exp(-|x|))
        float s  = __fdividef(1.0f, 1.0f + e);      // sigmoid(|x|)
        float p  = (x >= 0.0f) ? s : (1.0f - s);    // sigmoid(x)
        float one_m_pt = t ? (1.0f - p) : p;        // 1 - p_t
        float ce = sp + fmaxf(t ? -x : x, 0.0f);    // stable BCE-with-logits
        float at = t ? 0.25f : 0.75f;
        fl += at * one_m_pt * one_m_pt * ce;
    }

    // Per-block partials (deterministic reductions)
    float r0 = block_reduce(bce,  red);
    float r1 = block_reduce(posf, red);
    float r2 = block_reduce(bbox, red);
    float r3 = block_reduce(fl,   red);
    if (tid == 0) {
        g_part[blockIdx.x * 4 + 0] = r0;
        g_part[blockIdx.x * 4 + 1] = r1;
        g_part[blockIdx.x * 4 + 2] = r2;
        g_part[blockIdx.x * 4 + 3] = r3;
    }
}

__global__ void __launch_bounds__(1024) loss_final(float* __restrict__ out) {
    __shared__ float sh[4][1024];
    int tid = threadIdx.x;           // 1024 = 8 images x 128 slots
    int k   = tid & 127;
    float v0 = 0, v1 = 0, v2 = 0, v3 = 0;
    if (k < NBLK_PER_IMG) {
        int b = (tid >> 7) * NBLK_PER_IMG + k;
        v0 = g_part[b * 4 + 0];
        v1 = g_part[b * 4 + 1];
        v2 = g_part[b * 4 + 2];
        v3 = g_part[b * 4 + 3];
    }
    sh[0][tid] = v0; sh[1][tid] = v1; sh[2][tid] = v2; sh[3][tid] = v3;
    __syncthreads();
    #pragma unroll
    for (int s = 64; s > 0; s >>= 1) {
        if (k < s) {
            sh[0][tid] += sh[0][tid + s];
            sh[1][tid] += sh[1][tid + s];
            sh[2][tid] += sh[2][tid + s];
            sh[3][tid] += sh[3][tid + s];
        }
        __syncthreads();
    }
    if (tid == 0) {
        float obj_sum = 0, bbox_sum = 0, cls_sum = 0, num_pos = 0;
        #pragma unroll
        for (int i = 0; i < NIMG; i++) {
            float bce = sh[0][i * 128];
            float pc  = sh[1][i * 128];
            float bb  = sh[2][i * 128];
            float fls = sh[3][i * 128];
            obj_sum  += bce * (1.0f * pc + 0.5f * ((float)NANCH - pc));
            bbox_sum += bb;
            cls_sum  += fls / fmaxf(pc * (float)NCLS, 1.0f);
            num_pos  += pc;
        }
        num_pos = fmaxf(num_pos, 1.0f);
        out[0] = obj_sum / (float)NIMG
               + 5.0f * bbox_sum / num_pos
               + cls_sum / (float)NIMG;
    }
}

extern "C" void kernel_launch(void* const* d_in, const int* in_sizes, int n_in,
                              void* d_out, int out_size) {
    const float* obj   = (const float*)d_in[0];
    const float* boxes = (const float*)d_in[1];
    const float* cls   = (const float*)d_in[2];
    const float* tbox  = (const float*)d_in[3];
    const int*   tlab  = (const int*)d_in[4];
    float* out = (float*)d_out;

    loss_main<<<NBLOCKS, THREADS>>>(obj, boxes, cls, tbox, tlab);
    loss_final<<<1, 1024>>>(out);
}